// round 8
// baseline (speedup 1.0000x reference)
#include <cuda_runtime.h>
#include <cuda_bf16.h>
#include <math.h>
#include <cstdint>

#define N 4096
#define D 128
#define NCLS 512
#define MAXS 64      // loss same-class list cap
#define MAXPR 64     // reward pos cap
#define QSTR 128     // query stride (2*MAXPR)
#define ENC_NINF 0x007FFFFFu

typedef unsigned long long ull;

// ---- device scratch ----
__device__ float g_loss[N], g_reward[N];
__device__ int   g_cntR[NCLS], g_cntL[NCLS];
__device__ int   g_startR[NCLS + 1], g_startL[NCLS + 1];
__device__ int   g_memR[N], g_memL[N];
__device__ unsigned g_nmax[N];
__device__ float g_negsum[N];
__device__ float g_pt[N];
__device__ float g_lposv[(size_t)N * MAXS];
__device__ int   g_lposj[(size_t)N * MAXS];
__device__ int   g_lposn[N];
__device__ float g_qv[(size_t)N * QSTR];     // padded with -1e30
__device__ float g_tP[(size_t)N * MAXPR];
__device__ int   g_qn[N];                    // = 2*npos_reward
__device__ float g_sQ[(size_t)N * QSTR];
__device__ __nv_bfloat16 g_colhi[N * D], g_collo[N * D];
__device__ __nv_bfloat16 g_rowhi[N * D], g_rowlo[N * D];

__device__ __forceinline__ unsigned fenc(float x){
    unsigned u = __float_as_uint(x);
    return (u & 0x80000000u) ? ~u : (u | 0x80000000u);
}
__device__ __forceinline__ float fdec(unsigned e){
    unsigned u = (e & 0x80000000u) ? (e & 0x7FFFFFFFu) : ~e;
    return __uint_as_float(u);
}
__device__ __forceinline__ float binval(float s){
    return fminf(fmaxf(fmaf(s, -800.f, 800.f), 0.f), 1600.f);
}
__device__ __forceinline__ uint32_t smem_u32(const void* p){
    uint32_t a;
    asm("{ .reg .u64 t; cvta.to.shared.u64 t, %1; cvt.u32.u64 %0, t; }" : "=r"(a) : "l"(p));
    return a;
}
__device__ __forceinline__ float wredsum(float d){
#pragma unroll
    for (int o = 16; o; o >>= 1) d += __shfl_down_sync(0xffffffffu, d, o);
    return d;
}

// ---------------- setup: counts + both CSRs + init ----------------
__global__ void setup_kernel(const int* __restrict__ tr, const int* __restrict__ rl){
    __shared__ int cR[NCLS], cL[NCLS];
    __shared__ int wR[16], wL[16];
    int t = threadIdx.x;           // 512 = NCLS
    cR[t] = 0; cL[t] = 0;
    __syncthreads();
    for (int i = t; i < N; i += 512){
        atomicAdd(&cR[tr[i]], 1);
        atomicAdd(&cL[rl[i]], 1);
        g_nmax[i] = ENC_NINF;
        g_negsum[i] = 0.f;
    }
    __syncthreads();
    int lane = t & 31, warp = t >> 5;
    int vR = cR[t], vL = cL[t];
    g_cntR[t] = vR; g_cntL[t] = vL;
    int sR = vR, sL = vL;
#pragma unroll
    for (int o = 1; o < 32; o <<= 1){
        int uR = __shfl_up_sync(0xffffffffu, sR, o);
        int uL = __shfl_up_sync(0xffffffffu, sL, o);
        if (lane >= o){ sR += uR; sL += uL; }
    }
    if (lane == 31){ wR[warp] = sR; wL[warp] = sL; }
    __syncthreads();
    if (t == 0){
        int rR = 0, rL = 0;
        for (int w = 0; w < 16; w++){
            int a = wR[w], b = wL[w];
            wR[w] = rR; wL[w] = rL;
            rR += a; rL += b;
        }
        g_startR[NCLS] = rR; g_startL[NCLS] = rL;
    }
    __syncthreads();
    int excR = wR[warp] + sR - vR;
    int excL = wL[warp] + sL - vL;
    g_startR[t] = excR; g_startL[t] = excL;
    cR[t] = excR; cL[t] = excL;
    __syncthreads();
    for (int i = t; i < N; i += 512){
        int p = atomicAdd(&cR[tr[i]], 1); g_memR[p] = i;
        int q = atomicAdd(&cL[rl[i]], 1); g_memL[q] = i;
    }
}

// ---------------- split prep ----------------
__global__ void split_kernel(const float* __restrict__ col, const float* __restrict__ row){
    int i = blockIdx.x * 256 + threadIdx.x;
    float c = col[i], r = row[i];
    __nv_bfloat16 ch = __float2bfloat16(c);
    __nv_bfloat16 rh = __float2bfloat16(r);
    g_colhi[i] = ch; g_collo[i] = __float2bfloat16(c - __bfloat162float(ch));
    g_rowhi[i] = rh; g_rowlo[i] = __float2bfloat16(r - __bfloat162float(rh));
}

// ---------------- posdot_loss: fp32 pos sims (tr-classes) + pt ----------------
__global__ void posdot_loss(const int* __restrict__ tc,
                            const float* __restrict__ col, const float* __restrict__ row){
    const int warp = threadIdx.x >> 5, lane = threadIdx.x & 31;
    const int i = blockIdx.x * 8 + warp;
    const int c = tc[i];
    const int s0 = g_startR[c];
    const int cnt = min(g_startR[c + 1] - s0, MAXS);
    float4 a = *(const float4*)&col[(size_t)i * D + lane * 4];
    float pm = -INFINITY;
    for (int k = 0; k < cnt; k++){
        int j = g_memR[s0 + k];
        float4 b = *(const float4*)&row[(size_t)j * D + lane * 4];
        float d = a.x*b.x + a.y*b.y + a.z*b.z + a.w*b.w;
        d = wredsum(d);
        if (lane == 0){
            g_lposv[(size_t)i * MAXS + k] = d;
            g_lposj[(size_t)i * MAXS + k] = j;
            if (j != i) pm = fmaxf(pm, d);
        }
    }
    if (lane == 0){
        g_lposn[i] = cnt;
        g_pt[i] = fmaxf(0.6f, pm) - 0.1f;
    }
}

// ---------------- posdot_reward: fp32 pos sims (rl-classes) -> queries ----------------
__global__ void posdot_reward(const int* __restrict__ rl, const float* __restrict__ col){
    const int warp = threadIdx.x >> 5, lane = threadIdx.x & 31;
    const int i = blockIdx.x * 8 + warp;
    const int c = rl[i];
    const int s0 = g_startL[c];
    const int cnt = g_startL[c + 1] - s0;
    float4 a = *(const float4*)&col[(size_t)i * D + lane * 4];
    int np = 0;
    for (int k = 0; k < cnt && np < MAXPR; k++){
        int j = g_memL[s0 + k];
        if (j == i) continue;
        float4 b = *(const float4*)&col[(size_t)j * D + lane * 4];
        float d = a.x*b.x + a.y*b.y + a.z*b.z + a.w*b.w;
        d = wredsum(d);
        if (lane == 0){
            float t = binval(d);
            float e = floorf(t);
            g_tP[(size_t)i * MAXPR + np] = t;
            g_qv[(size_t)i * QSTR + 2*np]     = e + 1.0f;
            g_qv[(size_t)i * QSTR + 2*np + 1] = e + 2.0f;
        }
        np++;
    }
    if (lane == 0) g_qn[i] = 2 * np;
    // pad queries + zero sQ
    for (int k = lane; k < QSTR; k += 32){
        if (k >= 2 * np) g_qv[(size_t)i * QSTR + k] = -1e30f;
        g_sQ[(size_t)i * QSTR + k] = 0.f;
    }
}

// ================= shared MMA core =================
#define SSTR 136

struct Frag { float c0[4][4], c1[4][4], c2[4][4], c3[4][4]; };

__device__ __forceinline__ void mma_tile(
    Frag& F, const __nv_bfloat16 (*sA)[128][SSTR], const __nv_bfloat16 (*sB)[128][SSTR],
    int wr, int wc, int lane)
{
#pragma unroll
    for (int mf = 0; mf < 4; mf++)
#pragma unroll
        for (int nf = 0; nf < 4; nf++){
            F.c0[mf][nf] = 0.f; F.c1[mf][nf] = 0.f; F.c2[mf][nf] = 0.f; F.c3[mf][nf] = 0.f;
        }
#pragma unroll
    for (int seg = 0; seg < 3; seg++){
        const int ai = (seg == 2) ? 1 : 0;
        const int bi = (seg == 1) ? 1 : 0;
#pragma unroll
        for (int ks = 0; ks < 8; ks++){
            const int k0 = ks * 16;
            uint32_t a[4][4];
#pragma unroll
            for (int mf = 0; mf < 4; mf++){
                int trow = wr * 64 + mf * 16 + (lane & 15);
                int tcol = k0 + (lane >> 4) * 8;
                uint32_t addr = smem_u32(&sA[ai][trow][tcol]);
                asm volatile("ldmatrix.sync.aligned.m8n8.x4.shared.b16 {%0,%1,%2,%3}, [%4];"
                    : "=r"(a[mf][0]), "=r"(a[mf][1]), "=r"(a[mf][2]), "=r"(a[mf][3])
                    : "r"(addr));
            }
            uint32_t b[4][2];
#pragma unroll
            for (int nf = 0; nf < 4; nf++){
                int trow = wc * 32 + nf * 8 + (lane & 7);
                int tcol = k0 + ((lane >> 3) & 1) * 8;
                uint32_t addr = smem_u32(&sB[bi][trow][tcol]);
                asm volatile("ldmatrix.sync.aligned.m8n8.x2.shared.b16 {%0,%1}, [%2];"
                    : "=r"(b[nf][0]), "=r"(b[nf][1]) : "r"(addr));
            }
#pragma unroll
            for (int mf = 0; mf < 4; mf++)
#pragma unroll
                for (int nf = 0; nf < 4; nf++){
                    asm volatile(
                        "mma.sync.aligned.m16n8k16.row.col.f32.bf16.bf16.f32 "
                        "{%0,%1,%2,%3}, {%4,%5,%6,%7}, {%8,%9}, {%0,%1,%2,%3};"
                        : "+f"(F.c0[mf][nf]), "+f"(F.c1[mf][nf]),
                          "+f"(F.c2[mf][nf]), "+f"(F.c3[mf][nf])
                        : "r"(a[mf][0]), "r"(a[mf][1]), "r"(a[mf][2]), "r"(a[mf][3]),
                          "r"(b[nf][0]), "r"(b[nf][1]));
                }
        }
    }
}

// ---------------- loss GEMM: epilogue = neg_max + label-free threshold sum ----------------
__global__ __launch_bounds__(256, 1) void gemm_loss(
    const int* __restrict__ tc, const int* __restrict__ tr)
{
    __shared__ __nv_bfloat16 sA[2][128][SSTR];
    __shared__ __nv_bfloat16 sB[2][128][SSTR];
    __shared__ int tcs[128], trs[128];
    __shared__ unsigned nme[128];
    __shared__ float pts[128], lsum[128];

    const int tid  = threadIdx.x;
    const int wid  = tid >> 5;
    const int lane = tid & 31;
    const int row0 = blockIdx.y * 128;
    const int col0 = blockIdx.x * 128;

    if (tid < 128){
        tcs[tid] = tc[row0 + tid];
        trs[tid] = tr[col0 + tid];
        nme[tid] = ENC_NINF;
        pts[tid] = g_pt[row0 + tid];
        lsum[tid] = 0.f;
    }
#pragma unroll
    for (int it = 0; it < 8; it++){
        int u = tid + it * 256;
        int r = u >> 4, c = (u & 15) * 8;
        *(float4*)&sA[0][r][c] = *(const float4*)&g_colhi[(row0 + r) * D + c];
        *(float4*)&sA[1][r][c] = *(const float4*)&g_collo[(row0 + r) * D + c];
        *(float4*)&sB[0][r][c] = *(const float4*)&g_rowhi[(col0 + r) * D + c];
        *(float4*)&sB[1][r][c] = *(const float4*)&g_rowlo[(col0 + r) * D + c];
    }
    __syncthreads();

    const int wr = wid & 1, wc = wid >> 1;
    Frag F;
    mma_tile(F, sA, sB, wr, wc, lane);

    const int g = lane >> 2, t = lane & 3;

    int lab[8];
#pragma unroll
    for (int nf = 0; nf < 4; nf++){
        lab[nf*2]   = trs[wc * 32 + nf * 8 + 2 * t];
        lab[nf*2+1] = trs[wc * 32 + nf * 8 + 2 * t + 1];
    }

#pragma unroll
    for (int mf = 0; mf < 4; mf++){
#pragma unroll
        for (int hf = 0; hf < 2; hf++){
            int lrow = wr * 64 + mf * 16 + hf * 8 + g;
            int tcv  = tcs[lrow];
            float pt = pts[lrow];
            float nm = -INFINITY, ss = 0.f;
#pragma unroll
            for (int nf = 0; nf < 4; nf++){
                float v0 = hf ? F.c2[mf][nf] : F.c0[mf][nf];
                float v1 = hf ? F.c3[mf][nf] : F.c1[mf][nf];
                if (lab[nf*2]   != tcv) nm = fmaxf(nm, v0);
                if (lab[nf*2+1] != tcv) nm = fmaxf(nm, v1);
                if (v0 > pt) ss += v0;
                if (v1 > pt) ss += v1;
            }
            nm = fmaxf(nm, __shfl_down_sync(0xffffffffu, nm, 1));
            nm = fmaxf(nm, __shfl_down_sync(0xffffffffu, nm, 2));
            ss += __shfl_down_sync(0xffffffffu, ss, 1);
            ss += __shfl_down_sync(0xffffffffu, ss, 2);
            if (t == 0){
                atomicMax(&nme[lrow], fenc(nm));
                atomicAdd(&lsum[lrow], ss);
            }
        }
    }
    __syncthreads();
    if (tid < 128){
        atomicMax(&g_nmax[row0 + tid], nme[tid]);
        atomicAdd(&g_negsum[row0 + tid], lsum[tid]);
    }
}

// ---------------- symmetric GEMM: epilogue = rank-query accumulation ----------------
__global__ __launch_bounds__(256, 1) void gemm_sym(){
    __shared__ __nv_bfloat16 sA[2][128][SSTR];
    __shared__ __nv_bfloat16 sB[2][128][SSTR];

    const int tid  = threadIdx.x;
    const int wid  = tid >> 5;
    const int lane = tid & 31;

    int b = blockIdx.x, bx = 0;
    while ((bx + 1) * (bx + 2) / 2 <= b) bx++;
    int by = b - bx * (bx + 1) / 2;
    const int row0 = by * 128;
    const int col0 = bx * 128;

#pragma unroll
    for (int it = 0; it < 8; it++){
        int u = tid + it * 256;
        int r = u >> 4, c = (u & 15) * 8;
        *(float4*)&sA[0][r][c] = *(const float4*)&g_colhi[(row0 + r) * D + c];
        *(float4*)&sA[1][r][c] = *(const float4*)&g_collo[(row0 + r) * D + c];
        *(float4*)&sB[0][r][c] = *(const float4*)&g_colhi[(col0 + r) * D + c];
        *(float4*)&sB[1][r][c] = *(const float4*)&g_collo[(col0 + r) * D + c];
    }
    __syncthreads();

    const int wr = wid & 1, wc = wid >> 1;
    Frag F;
    mma_tile(F, sA, sB, wr, wc, lane);

    const int g = lane >> 2, t = lane & 3;

    // convert values to bin coords in place; diag -> +inf (saturate gives 0)
#pragma unroll
    for (int mf = 0; mf < 4; mf++){
        int rA = row0 + wr * 64 + mf * 16 + g;
        int rB = rA + 8;
#pragma unroll
        for (int nf = 0; nf < 4; nf++){
            int cA = col0 + wc * 32 + nf * 8 + 2 * t;
            int cB = cA + 1;
            F.c0[mf][nf] = (rA == cA) ? 1e30f : binval(F.c0[mf][nf]);
            F.c1[mf][nf] = (rA == cB) ? 1e30f : binval(F.c1[mf][nf]);
            F.c2[mf][nf] = (rB == cA) ? 1e30f : binval(F.c2[mf][nf]);
            F.c3[mf][nf] = (rB == cB) ? 1e30f : binval(F.c3[mf][nf]);
        }
    }

    // row side: queries of the 8 row positions this thread touches
#pragma unroll
    for (int mf = 0; mf < 4; mf++){
#pragma unroll
        for (int hf = 0; hf < 2; hf++){
            int gr = row0 + wr * 64 + mf * 16 + hf * 8 + g;
            int qn = g_qn[gr];
            int km = qn;
#pragma unroll
            for (int o = 16; o; o >>= 1) km = max(km, __shfl_xor_sync(0xffffffffu, km, o));
            for (int k = 0; k < km; k++){
                float q = g_qv[(size_t)gr * QSTR + k];
                float a = 0.f;
#pragma unroll
                for (int nf = 0; nf < 4; nf++){
                    a += __saturatef(q - (hf ? F.c2[mf][nf] : F.c0[mf][nf]));
                    a += __saturatef(q - (hf ? F.c3[mf][nf] : F.c1[mf][nf]));
                }
                a += __shfl_down_sync(0xffffffffu, a, 1);
                a += __shfl_down_sync(0xffffffffu, a, 2);
                if (t == 0 && k < qn) atomicAdd(&g_sQ[(size_t)gr * QSTR + k], a);
            }
        }
    }

    // col side (off-diagonal tiles): queries of the 8 col positions
    if (bx != by){
#pragma unroll
        for (int nf = 0; nf < 4; nf++){
#pragma unroll
            for (int e = 0; e < 2; e++){
                int gc = col0 + wc * 32 + nf * 8 + 2 * t + e;
                int qn = g_qn[gc];
                int km = qn;
#pragma unroll
                for (int o = 16; o; o >>= 1) km = max(km, __shfl_xor_sync(0xffffffffu, km, o));
                for (int k = 0; k < km; k++){
                    float q = g_qv[(size_t)gc * QSTR + k];
                    float a = 0.f;
#pragma unroll
                    for (int mf = 0; mf < 4; mf++){
                        a += __saturatef(q - (e ? F.c1[mf][nf] : F.c0[mf][nf]));
                        a += __saturatef(q - (e ? F.c3[mf][nf] : F.c2[mf][nf]));
                    }
                    a += __shfl_down_sync(0xffffffffu, a, 4);
                    a += __shfl_down_sync(0xffffffffu, a, 8);
                    a += __shfl_down_sync(0xffffffffu, a, 16);
                    if (g == 0 && k < qn) atomicAdd(&g_sQ[(size_t)gc * QSTR + k], a);
                }
            }
        }
    }
}

// ---------------- assemble: per-row loss fixups + AP ----------------
__global__ void assemble_kernel(const int* __restrict__ tc, const int* __restrict__ tr,
                                const int* __restrict__ rl){
    const int warp = threadIdx.x >> 5, lane = threadIdx.x & 31;
    const int i = blockIdx.x * 8 + warp;

    // loss
    float nthr = fdec(g_nmax[i]) + 0.1f;
    float pt   = g_pt[i];
    int   ns   = g_lposn[i];
    float fix = 0.f;
    for (int k = lane; k < ns; k += 32){
        float v = g_lposv[(size_t)i * MAXS + k];
        int   j = g_lposj[(size_t)i * MAXS + k];
        if (v > pt) fix -= v;                      // remove same-class from label-free sum
        if (j != i && v < nthr) fix += 1.0f - v;   // pos loss
    }
    fix = wredsum(fix);

    // reward AP
    int np = g_qn[i] >> 1;
    float ap = 0.f;
    for (int p = lane; p < np; p += 32){
        float tp = g_tP[(size_t)i * MAXPR + p];
        float e  = floorf(tp);
        float fr = tp - e;
        float u0 = e + 1.0f, u1 = e + 2.0f;
        float HP0 = 0.f, HP1 = 0.f;
        for (int q = 0; q < np; q++){
            float tq = g_tP[(size_t)i * MAXPR + q];
            HP0 += __saturatef(u0 - tq);
            HP1 += __saturatef(u1 - tq);
        }
        float HA0 = g_sQ[(size_t)i * QSTR + 2*p];
        float HA1 = g_sQ[(size_t)i * QSTR + 2*p + 1];
        float term = 0.f;
        if (HA0 > 0.f) term += (1.0f - fr) * HP0 / HA0;
        if (fr > 0.f && HA1 > 0.f) term += fr * HP1 / HA1;
        ap += term;
    }
    ap = wredsum(ap);

    if (lane == 0){
        int c = tc[i];
        int npos = g_cntR[c] - ((tr[i] == c) ? 1 : 0);
        g_loss[i] = (npos > 0) ? g_negsum[i] + fix : 0.f;
        int nl = g_cntL[rl[i]] - 1;
        g_reward[i] = (nl > 0) ? ap / (float)nl : 0.f;
    }
}

// ---------------- final scalar ----------------
__global__ void final_kernel(float* __restrict__ out){
    __shared__ float red[32];
    float s = 0.f;
    for (int i = threadIdx.x; i < N; i += blockDim.x)
        s += g_loss[i] * (1.0f - g_reward[i]);
    s = wredsum(s);
    int warp = threadIdx.x >> 5, lane = threadIdx.x & 31;
    if (lane == 0) red[warp] = s;
    __syncthreads();
    if (warp == 0){
        s = (lane < (int)(blockDim.x >> 5)) ? red[lane] : 0.f;
        s = wredsum(s);
        if (lane == 0) out[0] = s / (float)N;
    }
}

// ---------------- launch ----------------
extern "C" void kernel_launch(void* const* d_in, const int* in_sizes, int n_in,
                              void* d_out, int out_size)
{
    const float* inputs_col    = (const float*)d_in[0];
    const int*   targets_col   = (const int*)  d_in[1];
    const float* inputs_row    = (const float*)d_in[2];
    const int*   targets_row   = (const int*)  d_in[3];
    const int*   reward_labels = (const int*)  d_in[4];
    float* out = (float*)d_out;

    setup_kernel<<<1, 512>>>(targets_row, reward_labels);
    split_kernel<<<2048, 256>>>(inputs_col, inputs_row);
    posdot_loss<<<512, 256>>>(targets_col, inputs_col, inputs_row);
    posdot_reward<<<512, 256>>>(reward_labels, inputs_col);
    gemm_loss<<<dim3(32, 32), 256>>>(targets_col, targets_row);
    gemm_sym<<<528, 256>>>();
    assemble_kernel<<<512, 256>>>(targets_col, targets_row, reward_labels);
    final_kernel<<<1, 256>>>(out);
}

// round 9
// speedup vs baseline: 2.2252x; 2.2252x over previous
#include <cuda_runtime.h>
#include <cuda_bf16.h>
#include <math.h>
#include <cstdint>

#define N 4096
#define D 128
#define NCLS 512
#define MAXS 64
#define MAXPR 64
#define ENC_NINF 0x007FFFFFu

typedef unsigned long long ull;

// ---- device scratch ----
__device__ float g_sim[(size_t)N * N];       // reward GEMM output only
__device__ float g_loss[N], g_reward[N];
__device__ int   g_cntR[NCLS], g_cntL[NCLS];
__device__ int   g_startR[NCLS + 1], g_startL[NCLS + 1];
__device__ int   g_memR[N], g_memL[N];
__device__ unsigned g_nmax[N];
__device__ float g_negsum[N];
__device__ float g_pt[N];
__device__ float g_lposv[(size_t)N * MAXS];
__device__ int   g_lposj[(size_t)N * MAXS];
__device__ int   g_lposn[N];
__device__ __nv_bfloat16 g_colhi[N * D], g_collo[N * D];
__device__ __nv_bfloat16 g_rowhi[N * D], g_rowlo[N * D];

__device__ __forceinline__ unsigned fenc(float x){
    unsigned u = __float_as_uint(x);
    return (u & 0x80000000u) ? ~u : (u | 0x80000000u);
}
__device__ __forceinline__ float fdec(unsigned e){
    unsigned u = (e & 0x80000000u) ? (e & 0x7FFFFFFFu) : ~e;
    return __uint_as_float(u);
}
__device__ __forceinline__ float binval(float s){
    return fminf(fmaxf(fmaf(s, -800.f, 800.f), 0.f), 1600.f);
}
__device__ __forceinline__ uint32_t smem_u32(const void* p){
    uint32_t a;
    asm("{ .reg .u64 t; cvta.to.shared.u64 t, %1; cvt.u32.u64 %0, t; }" : "=r"(a) : "l"(p));
    return a;
}
__device__ __forceinline__ float wredsum(float d){
#pragma unroll
    for (int o = 16; o; o >>= 1) d += __shfl_down_sync(0xffffffffu, d, o);
    return d;
}

// ---------------- setup: counts + both CSRs + init ----------------
__global__ void setup_kernel(const int* __restrict__ tr, const int* __restrict__ rl){
    __shared__ int cR[NCLS], cL[NCLS];
    __shared__ int wR[16], wL[16];
    int t = threadIdx.x;           // 512 = NCLS
    cR[t] = 0; cL[t] = 0;
    __syncthreads();
    for (int i = t; i < N; i += 512){
        atomicAdd(&cR[tr[i]], 1);
        atomicAdd(&cL[rl[i]], 1);
        g_nmax[i] = ENC_NINF;
        g_negsum[i] = 0.f;
    }
    __syncthreads();
    int lane = t & 31, warp = t >> 5;
    int vR = cR[t], vL = cL[t];
    g_cntR[t] = vR; g_cntL[t] = vL;
    int sR = vR, sL = vL;
#pragma unroll
    for (int o = 1; o < 32; o <<= 1){
        int uR = __shfl_up_sync(0xffffffffu, sR, o);
        int uL = __shfl_up_sync(0xffffffffu, sL, o);
        if (lane >= o){ sR += uR; sL += uL; }
    }
    if (lane == 31){ wR[warp] = sR; wL[warp] = sL; }
    __syncthreads();
    if (t == 0){
        int rR = 0, rL = 0;
        for (int w = 0; w < 16; w++){
            int a = wR[w], b = wL[w];
            wR[w] = rR; wL[w] = rL;
            rR += a; rL += b;
        }
        g_startR[NCLS] = rR; g_startL[NCLS] = rL;
    }
    __syncthreads();
    int excR = wR[warp] + sR - vR;
    int excL = wL[warp] + sL - vL;
    g_startR[t] = excR; g_startL[t] = excL;
    cR[t] = excR; cL[t] = excL;
    __syncthreads();
    for (int i = t; i < N; i += 512){
        int p = atomicAdd(&cR[tr[i]], 1); g_memR[p] = i;
        int q = atomicAdd(&cL[rl[i]], 1); g_memL[q] = i;
    }
}

// ---------------- split prep ----------------
__global__ void split_kernel(const float* __restrict__ col, const float* __restrict__ row){
    int i = blockIdx.x * 256 + threadIdx.x;
    float c = col[i], r = row[i];
    __nv_bfloat16 ch = __float2bfloat16(c);
    __nv_bfloat16 rh = __float2bfloat16(r);
    g_colhi[i] = ch; g_collo[i] = __float2bfloat16(c - __bfloat162float(ch));
    g_rowhi[i] = rh; g_rowlo[i] = __float2bfloat16(r - __bfloat162float(rh));
}

// ---------------- posdot_loss: fp32 pos sims (tr-classes) + pt ----------------
__global__ void posdot_loss(const int* __restrict__ tc,
                            const float* __restrict__ col, const float* __restrict__ row){
    const int warp = threadIdx.x >> 5, lane = threadIdx.x & 31;
    const int i = blockIdx.x * 8 + warp;
    const int c = tc[i];
    const int s0 = g_startR[c];
    const int cnt = min(g_startR[c + 1] - s0, MAXS);
    float4 a = *(const float4*)&col[(size_t)i * D + lane * 4];
    float pm = -INFINITY;
    for (int k = 0; k < cnt; k++){
        int j = g_memR[s0 + k];
        float4 b = *(const float4*)&row[(size_t)j * D + lane * 4];
        float d = a.x*b.x + a.y*b.y + a.z*b.z + a.w*b.w;
        d = wredsum(d);
        if (lane == 0){
            g_lposv[(size_t)i * MAXS + k] = d;
            g_lposj[(size_t)i * MAXS + k] = j;
            if (j != i) pm = fmaxf(pm, d);
        }
    }
    if (lane == 0){
        g_lposn[i] = cnt;
        g_pt[i] = fmaxf(0.6f, pm) - 0.1f;
    }
}

// ================= shared MMA core =================
#define SSTR 136

struct Frag { float c0[4][4], c1[4][4], c2[4][4], c3[4][4]; };

__device__ __forceinline__ void mma_tile(
    Frag& F, const __nv_bfloat16 (*sA)[128][SSTR], const __nv_bfloat16 (*sB)[128][SSTR],
    int wr, int wc, int lane)
{
#pragma unroll
    for (int mf = 0; mf < 4; mf++)
#pragma unroll
        for (int nf = 0; nf < 4; nf++){
            F.c0[mf][nf] = 0.f; F.c1[mf][nf] = 0.f; F.c2[mf][nf] = 0.f; F.c3[mf][nf] = 0.f;
        }
#pragma unroll
    for (int seg = 0; seg < 3; seg++){
        const int ai = (seg == 2) ? 1 : 0;
        const int bi = (seg == 1) ? 1 : 0;
#pragma unroll
        for (int ks = 0; ks < 8; ks++){
            const int k0 = ks * 16;
            uint32_t a[4][4];
#pragma unroll
            for (int mf = 0; mf < 4; mf++){
                int trow = wr * 64 + mf * 16 + (lane & 15);
                int tcol = k0 + (lane >> 4) * 8;
                uint32_t addr = smem_u32(&sA[ai][trow][tcol]);
                asm volatile("ldmatrix.sync.aligned.m8n8.x4.shared.b16 {%0,%1,%2,%3}, [%4];"
                    : "=r"(a[mf][0]), "=r"(a[mf][1]), "=r"(a[mf][2]), "=r"(a[mf][3])
                    : "r"(addr));
            }
            uint32_t b[4][2];
#pragma unroll
            for (int nf = 0; nf < 4; nf++){
                int trow = wc * 32 + nf * 8 + (lane & 7);
                int tcol = k0 + ((lane >> 3) & 1) * 8;
                uint32_t addr = smem_u32(&sB[bi][trow][tcol]);
                asm volatile("ldmatrix.sync.aligned.m8n8.x2.shared.b16 {%0,%1}, [%2];"
                    : "=r"(b[nf][0]), "=r"(b[nf][1]) : "r"(addr));
            }
#pragma unroll
            for (int mf = 0; mf < 4; mf++)
#pragma unroll
                for (int nf = 0; nf < 4; nf++){
                    asm volatile(
                        "mma.sync.aligned.m16n8k16.row.col.f32.bf16.bf16.f32 "
                        "{%0,%1,%2,%3}, {%4,%5,%6,%7}, {%8,%9}, {%0,%1,%2,%3};"
                        : "+f"(F.c0[mf][nf]), "+f"(F.c1[mf][nf]),
                          "+f"(F.c2[mf][nf]), "+f"(F.c3[mf][nf])
                        : "r"(a[mf][0]), "r"(a[mf][1]), "r"(a[mf][2]), "r"(a[mf][3]),
                          "r"(b[nf][0]), "r"(b[nf][1]));
                }
        }
    }
}

// ---------------- loss GEMM: no sim store; epilogue = neg_max + threshold sum ----------------
__global__ __launch_bounds__(256, 1) void gemm_loss(
    const int* __restrict__ tc, const int* __restrict__ tr)
{
    __shared__ __nv_bfloat16 sA[2][128][SSTR];
    __shared__ __nv_bfloat16 sB[2][128][SSTR];
    __shared__ int tcs[128], trs[128];
    __shared__ unsigned nme[128];
    __shared__ float pts[128], lsum[128];

    const int tid  = threadIdx.x;
    const int wid  = tid >> 5;
    const int lane = tid & 31;
    const int row0 = blockIdx.y * 128;
    const int col0 = blockIdx.x * 128;

    if (tid < 128){
        tcs[tid] = tc[row0 + tid];
        trs[tid] = tr[col0 + tid];
        nme[tid] = ENC_NINF;
        pts[tid] = g_pt[row0 + tid];
        lsum[tid] = 0.f;
    }
#pragma unroll
    for (int it = 0; it < 8; it++){
        int u = tid + it * 256;
        int r = u >> 4, c = (u & 15) * 8;
        *(float4*)&sA[0][r][c] = *(const float4*)&g_colhi[(row0 + r) * D + c];
        *(float4*)&sA[1][r][c] = *(const float4*)&g_collo[(row0 + r) * D + c];
        *(float4*)&sB[0][r][c] = *(const float4*)&g_rowhi[(col0 + r) * D + c];
        *(float4*)&sB[1][r][c] = *(const float4*)&g_rowlo[(col0 + r) * D + c];
    }
    __syncthreads();

    const int wr = wid & 1, wc = wid >> 1;
    Frag F;
    mma_tile(F, sA, sB, wr, wc, lane);

    const int g = lane >> 2, t = lane & 3;

    int lab[8];
#pragma unroll
    for (int nf = 0; nf < 4; nf++){
        lab[nf*2]   = trs[wc * 32 + nf * 8 + 2 * t];
        lab[nf*2+1] = trs[wc * 32 + nf * 8 + 2 * t + 1];
    }

#pragma unroll
    for (int mf = 0; mf < 4; mf++){
#pragma unroll
        for (int hf = 0; hf < 2; hf++){
            int lrow = wr * 64 + mf * 16 + hf * 8 + g;
            int tcv  = tcs[lrow];
            float pt = pts[lrow];
            float nm = -INFINITY, ss = 0.f;
#pragma unroll
            for (int nf = 0; nf < 4; nf++){
                float v0 = hf ? F.c2[mf][nf] : F.c0[mf][nf];
                float v1 = hf ? F.c3[mf][nf] : F.c1[mf][nf];
                if (lab[nf*2]   != tcv) nm = fmaxf(nm, v0);
                if (lab[nf*2+1] != tcv) nm = fmaxf(nm, v1);
                if (v0 > pt) ss += v0;
                if (v1 > pt) ss += v1;
            }
            nm = fmaxf(nm, __shfl_down_sync(0xffffffffu, nm, 1));
            nm = fmaxf(nm, __shfl_down_sync(0xffffffffu, nm, 2));
            ss += __shfl_down_sync(0xffffffffu, ss, 1);
            ss += __shfl_down_sync(0xffffffffu, ss, 2);
            if (t == 0){
                atomicMax(&nme[lrow], fenc(nm));
                atomicAdd(&lsum[lrow], ss);
            }
        }
    }
    __syncthreads();
    if (tid < 128){
        atomicMax(&g_nmax[row0 + tid], nme[tid]);
        atomicAdd(&g_negsum[row0 + tid], lsum[tid]);
    }
}

// ---------------- loss finish: pos-list corrections ----------------
__global__ void loss_finish(const int* __restrict__ tc, const int* __restrict__ tr){
    const int warp = threadIdx.x >> 5, lane = threadIdx.x & 31;
    const int i = blockIdx.x * 8 + warp;
    float nthr = fdec(g_nmax[i]) + 0.1f;
    float pt   = g_pt[i];
    int   ns   = g_lposn[i];
    float fix = 0.f;
    for (int k = lane; k < ns; k += 32){
        float v = g_lposv[(size_t)i * MAXS + k];
        int   j = g_lposj[(size_t)i * MAXS + k];
        if (v > pt) fix -= v;                      // same-class wrongly summed
        if (j != i && v < nthr) fix += 1.0f - v;   // pos loss
    }
    fix = wredsum(fix);
    if (lane == 0){
        int c = tc[i];
        int npos = g_cntR[c] - ((tr[i] == c) ? 1 : 0);
        g_loss[i] = (npos > 0) ? g_negsum[i] + fix : 0.f;
    }
}

// ---------------- symmetric GEMM (R7): store sim, triangular + transpose ----------------
__global__ __launch_bounds__(256, 1) void gemm_sym(){
    __shared__ __nv_bfloat16 sA[2][128][SSTR];
    __shared__ __nv_bfloat16 sB[2][128][SSTR];

    const int tid  = threadIdx.x;
    const int wid  = tid >> 5;
    const int lane = tid & 31;

    int b = blockIdx.x, bx = 0;
    while ((bx + 1) * (bx + 2) / 2 <= b) bx++;
    int by = b - bx * (bx + 1) / 2;
    const int row0 = by * 128;
    const int col0 = bx * 128;

#pragma unroll
    for (int it = 0; it < 8; it++){
        int u = tid + it * 256;
        int r = u >> 4, c = (u & 15) * 8;
        *(float4*)&sA[0][r][c] = *(const float4*)&g_colhi[(row0 + r) * D + c];
        *(float4*)&sA[1][r][c] = *(const float4*)&g_collo[(row0 + r) * D + c];
        *(float4*)&sB[0][r][c] = *(const float4*)&g_colhi[(col0 + r) * D + c];
        *(float4*)&sB[1][r][c] = *(const float4*)&g_collo[(col0 + r) * D + c];
    }
    __syncthreads();

    const int wr = wid & 1, wc = wid >> 1;
    Frag F;
    mma_tile(F, sA, sB, wr, wc, lane);

    const int g = lane >> 2, t = lane & 3;

#pragma unroll
    for (int mf = 0; mf < 4; mf++){
        int rA = row0 + wr * 64 + mf * 16 + g;
#pragma unroll
        for (int nf = 0; nf < 4; nf++){
            int cc = col0 + wc * 32 + nf * 8 + 2 * t;
            *(float2*)&g_sim[(size_t)rA * N + cc]       = make_float2(F.c0[mf][nf], F.c1[mf][nf]);
            *(float2*)&g_sim[(size_t)(rA + 8) * N + cc] = make_float2(F.c2[mf][nf], F.c3[mf][nf]);
        }
    }

    if (bx != by){
        float* stg = (float*)&sA[0][0][0];   // [128][132]
        __syncthreads();
#pragma unroll
        for (int mf = 0; mf < 4; mf++){
            int rr = wr * 64 + mf * 16 + g;
#pragma unroll
            for (int nf = 0; nf < 4; nf++){
                int cc = wc * 32 + nf * 8 + 2 * t;
                stg[(cc    ) * 132 + rr]     = F.c0[mf][nf];
                stg[(cc + 1) * 132 + rr]     = F.c1[mf][nf];
                stg[(cc    ) * 132 + rr + 8] = F.c2[mf][nf];
                stg[(cc + 1) * 132 + rr + 8] = F.c3[mf][nf];
            }
        }
        __syncthreads();
#pragma unroll
        for (int it = 0; it < 16; it++){
            int u = tid + it * 256;
            int r = u >> 5, c4 = (u & 31) * 4;
            float4 v = *(const float4*)&stg[r * 132 + c4];
            *(float4*)&g_sim[(size_t)(col0 + r) * N + row0 + c4] = v;
        }
    }
}

// ---------------- reward: rank-query FastAP (R7) ----------------
__global__ __launch_bounds__(256) void reward_ap(const int* __restrict__ rl){
    __shared__ float tP[MAXPR];
    __shared__ float qv[2 * MAXPR];
    __shared__ float sQ[2 * MAXPR];
    __shared__ int   np_s;
    __shared__ float s_ap;

    const int tid = threadIdx.x, lane = tid & 31;
    const int i = blockIdx.x;
    const int c = rl[i];
    const float* row = g_sim + (size_t)i * N;

    if (tid == 0){ np_s = 0; s_ap = 0.f; }
    if (tid < 2 * MAXPR) sQ[tid] = 0.f;
    __syncthreads();

    {
        int s0 = g_startL[c], cnt = g_startL[c + 1] - s0;
        if (tid < cnt){
            int j = g_memL[s0 + tid];
            if (j != i){
                float t = binval(row[j]);
                int k = atomicAdd(&np_s, 1);
                if (k < MAXPR){
                    tP[k] = t;
                    float e = floorf(t);
                    qv[2*k]   = e + 1.0f;
                    qv[2*k+1] = e + 2.0f;
                }
            }
        }
    }
    __syncthreads();
    const int npos = min(np_s, MAXPR);
    const int K = 2 * npos;

    float t[16];
#pragma unroll
    for (int it = 0; it < 4; it++){
        int j4 = tid + it * 256;
        float4 v = *((const float4*)row + j4);
        int j = j4 * 4;
        t[it*4+0] = (j+0 == i) ? 1e30f : binval(v.x);
        t[it*4+1] = (j+1 == i) ? 1e30f : binval(v.y);
        t[it*4+2] = (j+2 == i) ? 1e30f : binval(v.z);
        t[it*4+3] = (j+3 == i) ? 1e30f : binval(v.w);
    }

    for (int k = 0; k < K; k++){
        float q = qv[k];
        float a = 0.f;
#pragma unroll
        for (int m = 0; m < 16; m++) a += __saturatef(q - t[m]);
        a = wredsum(a);
        if (lane == 0) atomicAdd(&sQ[k], a);
    }
    __syncthreads();

    if (tid < npos){
        float tp = tP[tid];
        float u0 = qv[2*tid], u1 = qv[2*tid+1];
        float fr = tp - floorf(tp);
        float HP0 = 0.f, HP1 = 0.f;
        for (int q = 0; q < npos; q++){
            float tq = tP[q];
            HP0 += __saturatef(u0 - tq);
            HP1 += __saturatef(u1 - tq);
        }
        float HA0 = sQ[2*tid], HA1 = sQ[2*tid+1];
        float term = 0.f;
        if (HA0 > 0.f) term += (1.0f - fr) * HP0 / HA0;
        if (fr > 0.f && HA1 > 0.f) term += fr * HP1 / HA1;
        atomicAdd(&s_ap, term);
    }
    __syncthreads();
    if (tid == 0){
        int np = g_cntL[c] - 1;
        g_reward[i] = (np > 0) ? s_ap / (float)np : 0.f;
    }
}

// ---------------- final scalar ----------------
__global__ void final_kernel(float* __restrict__ out){
    __shared__ float red[32];
    float s = 0.f;
    for (int i = threadIdx.x; i < N; i += blockDim.x)
        s += g_loss[i] * (1.0f - g_reward[i]);
    s = wredsum(s);
    int warp = threadIdx.x >> 5, lane = threadIdx.x & 31;
    if (lane == 0) red[warp] = s;
    __syncthreads();
    if (warp == 0){
        s = (lane < (int)(blockDim.x >> 5)) ? red[lane] : 0.f;
        s = wredsum(s);
        if (lane == 0) out[0] = s / (float)N;
    }
}

// ---------------- launch ----------------
extern "C" void kernel_launch(void* const* d_in, const int* in_sizes, int n_in,
                              void* d_out, int out_size)
{
    const float* inputs_col    = (const float*)d_in[0];
    const int*   targets_col   = (const int*)  d_in[1];
    const float* inputs_row    = (const float*)d_in[2];
    const int*   targets_row   = (const int*)  d_in[3];
    const int*   reward_labels = (const int*)  d_in[4];
    float* out = (float*)d_out;

    setup_kernel<<<1, 512>>>(targets_row, reward_labels);
    split_kernel<<<2048, 256>>>(inputs_col, inputs_row);
    posdot_loss<<<512, 256>>>(targets_col, inputs_col, inputs_row);
    gemm_loss<<<dim3(32, 32), 256>>>(targets_col, targets_row);
    loss_finish<<<512, 256>>>(targets_col, targets_row);
    gemm_sym<<<528, 256>>>();
    reward_ap<<<4096, 256>>>(reward_labels);
    final_kernel<<<1, 256>>>(out);
}